// round 17
// baseline (speedup 1.0000x reference)
#include <cuda_runtime.h>
#include <math.h>

#define HEADS 8
#define DHEAD 40
#define CMODEL 320
#define CX 768
#define LSEQ 77
#define NB 10
#define HW 4096
#define NPHASE 9

typedef unsigned long long u64;

// ---------------- packed f32x2 helpers (FFMA2 path, sm_100+) ---------------
__device__ __forceinline__ u64 pack2(float lo, float hi) {
    u64 r; asm("mov.b64 %0, {%1, %2};" : "=l"(r) : "f"(lo), "f"(hi)); return r;
}
__device__ __forceinline__ float2 unpk2(u64 v) {
    float2 f; asm("mov.b64 {%0, %1}, %2;" : "=f"(f.x), "=f"(f.y) : "l"(v)); return f;
}
__device__ __forceinline__ u64 ffma2(u64 a, u64 b, u64 c) {
    u64 d; asm("fma.rn.f32x2 %0, %1, %2, %3;" : "=l"(d) : "l"(a), "l"(b), "l"(c)); return d;
}

// ---------------- scratch (device globals; no allocation allowed) ----------
__device__ __align__(16) float g_q[2 * HW * CMODEL];
__device__ __align__(16) float g_k[NB * LSEQ * CMODEL];
__device__ __align__(16) float g_v[NB * LSEQ * CMODEL];
__device__ __align__(16) float g_A[2 * HW * CMODEL];      // [0:HW)=uncond, [HW:2HW)=weighted sum
__device__ __align__(16) float g_O[NPHASE * HW * CMODEL]; // per-batch weighted outputs (b=1..9)
__device__ __align__(16) float g_w9[NPHASE * HW];
__device__ __align__(16) float g_wsum[HW];

// ---------------- phase weights (jax.image.resize bilinear+antialias) ------
__device__ __forceinline__ float resize_factor(int o, float lo, float hi) {
    float sf = (o + 0.5f) * 8.0f - 0.5f;
    float num = 0.f, den = 0.f;
    int h0 = o * 8 - 4, h1 = o * 8 + 11;
    #pragma unroll 1
    for (int h = h0; h <= h1; ++h) {
        if (h < 0 || h > 511) continue;
        float fh = (float)h;
        float wgt = 1.0f - fabsf(fh - sf) * 0.125f;
        den += wgt;
        if (fh >= lo && fh < hi) num += wgt;
    }
    return num / den;
}

__global__ void weights_kernel(const float* __restrict__ bboxes) {
    int p = blockIdx.x * blockDim.x + threadIdx.x;
    if (p >= HW) return;
    int r = p >> 6, c = p & 63;
    float s = 0.1f;
    g_w9[p] = 0.1f;
    #pragma unroll 1
    for (int i = 0; i < 8; ++i) {
        float x0 = bboxes[i * 4 + 0], y0 = bboxes[i * 4 + 1];
        float x1 = bboxes[i * 4 + 2], y1 = bboxes[i * 4 + 3];
        float wmin = floorf(512.f * x0), wmax = floorf(512.f * x1);
        float hmin = floorf(512.f * y0), hmax = floorf(512.f * y1);
        float wv = 10.f * resize_factor(r, hmin, hmax) * resize_factor(c, wmin, wmax);
        g_w9[(i + 1) * HW + p] = wv;
        s += wv;
    }
    g_wsum[p] = s;
}

// ---------------- fused K+V projection: 32x64 tile (125 blocks) ------------
__global__ void __launch_bounds__(256) kvproj_kernel(
    const float* __restrict__ ehs,
    const float* __restrict__ Wk, const float* __restrict__ Wv)
{
    __shared__ __align__(16) float As[16][36];
    __shared__ __align__(16) float Bk[16][64];
    __shared__ __align__(16) float Bv[16][64];
    const int tx = threadIdx.x, ty = threadIdx.y;
    const int t  = ty * 16 + tx;
    const int row0 = blockIdx.y * 32, col0 = blockIdx.x * 64;
    const int li = t >> 3, lk = (t & 7) << 1;    // A: 32 rows x 16 k, float2 each
    const int bk = t >> 4, bj = (t & 15) << 2;

    u64 ak[4], av[4];
    #pragma unroll
    for (int j = 0; j < 4; ++j) { ak[j] = 0ULL; av[j] = 0ULL; }

    for (int k0 = 0; k0 < CX; k0 += 16) {
        // rows up to 799 < 847 total in ehs — unguarded load is safe
        float2 a = *(const float2*)(ehs + (size_t)(row0 + li) * CX + k0 + lk);
        As[lk + 0][li] = a.x; As[lk + 1][li] = a.y;
        *(float4*)(&Bk[bk][bj]) = *(const float4*)(Wk + (size_t)(k0 + bk) * CMODEL + col0 + bj);
        *(float4*)(&Bv[bk][bj]) = *(const float4*)(Wv + (size_t)(k0 + bk) * CMODEL + col0 + bj);
        __syncthreads();
        #pragma unroll
        for (int kk = 0; kk < 16; ++kk) {
            u64 ap = *(const u64*)(&As[kk][ty * 2]);   // row pair (2ty, 2ty+1)
            float4 b1 = *(const float4*)(&Bk[kk][tx * 4]);
            float4 b2 = *(const float4*)(&Bv[kk][tx * 4]);
            ak[0] = ffma2(ap, pack2(b1.x, b1.x), ak[0]);
            ak[1] = ffma2(ap, pack2(b1.y, b1.y), ak[1]);
            ak[2] = ffma2(ap, pack2(b1.z, b1.z), ak[2]);
            ak[3] = ffma2(ap, pack2(b1.w, b1.w), ak[3]);
            av[0] = ffma2(ap, pack2(b2.x, b2.x), av[0]);
            av[1] = ffma2(ap, pack2(b2.y, b2.y), av[1]);
            av[2] = ffma2(ap, pack2(b2.z, b2.z), av[2]);
            av[3] = ffma2(ap, pack2(b2.w, b2.w), av[3]);
        }
        __syncthreads();
    }
    float2 c0 = unpk2(ak[0]), c1 = unpk2(ak[1]), c2 = unpk2(ak[2]), c3 = unpk2(ak[3]);
    float2 d0 = unpk2(av[0]), d1 = unpk2(av[1]), d2 = unpk2(av[2]), d3 = unpk2(av[3]);
    int re = row0 + ty * 2;
    if (re < NB * LSEQ) {
        *(float4*)(g_k + (size_t)re * CMODEL + col0 + tx * 4) = make_float4(c0.x, c1.x, c2.x, c3.x);
        *(float4*)(g_v + (size_t)re * CMODEL + col0 + tx * 4) = make_float4(d0.x, d1.x, d2.x, d3.x);
    }
    if (re + 1 < NB * LSEQ) {
        *(float4*)(g_k + (size_t)(re + 1) * CMODEL + col0 + tx * 4) = make_float4(c0.y, c1.y, c2.y, c3.y);
        *(float4*)(g_v + (size_t)(re + 1) * CMODEL + col0 + tx * 4) = make_float4(d0.y, d1.y, d2.y, d3.y);
    }
}

// ---------------- 128x64 GEMM core, splat-free FFMA2, double-buffered ------
// A stored ROW-DUPLICATED in smem ((a,a) u64 ready for ffma2), B read as
// natural column pairs. Per kk: 6 LDS.128 + 32 ffma2, zero packs.
// Thread (tx,ty): rows ty*8..+7, cols col0+tx*8..+7.
__device__ __forceinline__ void gemm128_f2(
    const float* __restrict__ A, const float* __restrict__ B,
    int K, int N, u64 (&acc)[8][4])
{
    __shared__ __align__(16) float As[2][16][256];   // [k][2*row] duplicated
    __shared__ __align__(16) float Bs[2][16][64];
    const int tx = threadIdx.x, ty = threadIdx.y;   // tx 0..7, ty 0..15
    const int t  = ty * 8 + tx;                     // 0..127
    const int row0 = blockIdx.y * 128, col0 = blockIdx.x * 64;
    const int bk = t >> 3, bj = (t & 7) << 3;       // B loader: 16 k-rows, 8 floats/thr

    #pragma unroll
    for (int i = 0; i < 8; ++i)
        #pragma unroll
        for (int j = 0; j < 4; ++j) acc[i][j] = 0ULL;

    const float* apg = A + (size_t)(row0 + t) * K;
    const float* bpg = B + (size_t)bk * N + col0 + bj;

    // stage tile 0 into buffer 0 (A duplicated via STS.64)
    {
        #pragma unroll
        for (int j = 0; j < 4; ++j) {
            float4 a = *(const float4*)(apg + 4 * j);
            u64* dst = (u64*)(&As[0][4 * j][0]) + t;       // u64 index t within k-row
            dst[0]   = pack2(a.x, a.x);
            dst[128] = pack2(a.y, a.y);                    // next k-row = 128 u64
            dst[256] = pack2(a.z, a.z);
            dst[384] = pack2(a.w, a.w);
        }
        *(float4*)(&Bs[0][bk][bj])     = *(const float4*)(bpg);
        *(float4*)(&Bs[0][bk][bj + 4]) = *(const float4*)(bpg + 4);
    }
    __syncthreads();

    int cur = 0;
    for (int k0 = 0; k0 < K; k0 += 16) {
        // prefetch next tile into regs (overlaps compute)
        float4 ar[4]; float4 br0, br1;
        const bool more = (k0 + 16 < K);
        if (more) {
            #pragma unroll
            for (int j = 0; j < 4; ++j) ar[j] = *(const float4*)(apg + k0 + 16 + 4 * j);
            br0 = *(const float4*)(bpg + (size_t)(k0 + 16) * N);
            br1 = *(const float4*)(bpg + (size_t)(k0 + 16) * N + 4);
        }

        #pragma unroll
        for (int kk = 0; kk < 16; ++kk) {
            // A: 4 LDS.128, each = two duplicated row-splats
            const ulonglong2* arow = (const ulonglong2*)(&As[cur][kk][ty * 16]);
            ulonglong2 a01 = arow[0], a23 = arow[1], a45 = arow[2], a67 = arow[3];
            // B: 2 LDS.128, each = two natural column-pairs
            const ulonglong2* brow = (const ulonglong2*)(&Bs[cur][kk][tx * 8]);
            ulonglong2 bA = brow[0], bB = brow[1];   // colpairs (0,1),(2,3)
            acc[0][0] = ffma2(a01.x, bA.x, acc[0][0]); acc[0][1] = ffma2(a01.x, bA.y, acc[0][1]);
            acc[0][2] = ffma2(a01.x, bB.x, acc[0][2]); acc[0][3] = ffma2(a01.x, bB.y, acc[0][3]);
            acc[1][0] = ffma2(a01.y, bA.x, acc[1][0]); acc[1][1] = ffma2(a01.y, bA.y, acc[1][1]);
            acc[1][2] = ffma2(a01.y, bB.x, acc[1][2]); acc[1][3] = ffma2(a01.y, bB.y, acc[1][3]);
            acc[2][0] = ffma2(a23.x, bA.x, acc[2][0]); acc[2][1] = ffma2(a23.x, bA.y, acc[2][1]);
            acc[2][2] = ffma2(a23.x, bB.x, acc[2][2]); acc[2][3] = ffma2(a23.x, bB.y, acc[2][3]);
            acc[3][0] = ffma2(a23.y, bA.x, acc[3][0]); acc[3][1] = ffma2(a23.y, bA.y, acc[3][1]);
            acc[3][2] = ffma2(a23.y, bB.x, acc[3][2]); acc[3][3] = ffma2(a23.y, bB.y, acc[3][3]);
            acc[4][0] = ffma2(a45.x, bA.x, acc[4][0]); acc[4][1] = ffma2(a45.x, bA.y, acc[4][1]);
            acc[4][2] = ffma2(a45.x, bB.x, acc[4][2]); acc[4][3] = ffma2(a45.x, bB.y, acc[4][3]);
            acc[5][0] = ffma2(a45.y, bA.x, acc[5][0]); acc[5][1] = ffma2(a45.y, bA.y, acc[5][1]);
            acc[5][2] = ffma2(a45.y, bB.x, acc[5][2]); acc[5][3] = ffma2(a45.y, bB.y, acc[5][3]);
            acc[6][0] = ffma2(a67.x, bA.x, acc[6][0]); acc[6][1] = ffma2(a67.x, bA.y, acc[6][1]);
            acc[6][2] = ffma2(a67.x, bB.x, acc[6][2]); acc[6][3] = ffma2(a67.x, bB.y, acc[6][3]);
            acc[7][0] = ffma2(a67.y, bA.x, acc[7][0]); acc[7][1] = ffma2(a67.y, bA.y, acc[7][1]);
            acc[7][2] = ffma2(a67.y, bB.x, acc[7][2]); acc[7][3] = ffma2(a67.y, bB.y, acc[7][3]);
        }

        if (more) {
            int nxt = cur ^ 1;
            #pragma unroll
            for (int j = 0; j < 4; ++j) {
                u64* dst = (u64*)(&As[nxt][4 * j][0]) + t;
                dst[0]   = pack2(ar[j].x, ar[j].x);
                dst[128] = pack2(ar[j].y, ar[j].y);
                dst[256] = pack2(ar[j].z, ar[j].z);
                dst[384] = pack2(ar[j].w, ar[j].w);
            }
            *(float4*)(&Bs[nxt][bk][bj])     = br0;
            *(float4*)(&Bs[nxt][bk][bj + 4]) = br1;
            __syncthreads();
            cur = nxt;
        }
    }
}

// Q projection: [8192,320] x [320,320] -> g_q
__global__ void __launch_bounds__(128) qproj_kernel(
    const float* __restrict__ hs, const float* __restrict__ Wq)
{
    u64 acc[8][4];
    gemm128_f2(hs, Wq, CMODEL, CMODEL, acc);
    const int row0 = blockIdx.y * 128, col0 = blockIdx.x * 64;
    const int tx = threadIdx.x, ty = threadIdx.y;
    #pragma unroll
    for (int i = 0; i < 8; ++i) {
        float2 c0 = unpk2(acc[i][0]), c1 = unpk2(acc[i][1]);
        float2 c2 = unpk2(acc[i][2]), c3 = unpk2(acc[i][3]);
        float* r = g_q + (size_t)(row0 + ty * 8 + i) * CMODEL + col0 + tx * 8;
        *(float4*)(r)     = make_float4(c0.x, c0.y, c1.x, c1.y);
        *(float4*)(r + 4) = make_float4(c2.x, c2.y, c3.x, c3.y);
    }
}

// Output projection + fused epilogue
__global__ void __launch_bounds__(128) outproj_kernel(
    const float* __restrict__ Wo, const float* __restrict__ bo,
    float* __restrict__ out)
{
    u64 acc[8][4];
    gemm128_f2(g_A, Wo, CMODEL, CMODEL, acc);
    const int row0 = blockIdx.y * 128, col0 = blockIdx.x * 64;
    const int tx = threadIdx.x, ty = threadIdx.y;
    const int cbase = col0 + tx * 8;
    float4 bA = *(const float4*)(bo + cbase);
    float4 bB = *(const float4*)(bo + cbase + 4);
    #pragma unroll
    for (int i = 0; i < 8; ++i) {
        float2 c0 = unpk2(acc[i][0]), c1 = unpk2(acc[i][1]);
        float2 c2 = unpk2(acc[i][2]), c3 = unpk2(acc[i][3]);
        int r = row0 + ty * 8 + i;
        float4 oA, oB;
        if (r < HW) {
            oA = make_float4(c0.x + bA.x, c0.y + bA.y, c1.x + bA.z, c1.y + bA.w);
            oB = make_float4(c2.x + bB.x, c2.y + bB.y, c3.x + bB.z, c3.y + bB.w);
        } else {
            float ws = g_wsum[r - HW];
            float invD = 1.f / (ws + 1e-6f);
            float bs = ws * invD;
            oA = make_float4(c0.x * invD + bA.x * bs, c0.y * invD + bA.y * bs,
                             c1.x * invD + bA.z * bs, c1.y * invD + bA.w * bs);
            oB = make_float4(c2.x * invD + bB.x * bs, c2.y * invD + bB.y * bs,
                             c3.x * invD + bB.z * bs, c3.y * invD + bB.w * bs);
        }
        float* o = out + (size_t)r * CMODEL + cbase;
        *(float4*)(o)     = oA;
        *(float4*)(o + 4) = oB;
    }
}

// ---------------- attention: thread-pair per pixel, 2-key unroll (R14) -----
__global__ void __launch_bounds__(256) att_kernel()
{
    __shared__ __align__(16) u64 ks[LSEQ * 20];   // 77 rows x 40 floats (20 u64)
    __shared__ __align__(16) u64 vs[LSEQ * 20];
    const int head = blockIdx.y;
    const int b = blockIdx.z;
    const int t = threadIdx.x;        // 0..255
    const int pl = t >> 1;            // local pixel 0..127
    const int half = t & 1;           // dim half: floats [half*20, half*20+20)
    const int p = blockIdx.x * 128 + pl;
    const float scale = 0.15811388300841897f;     // 1/sqrt(40)

    float wg = 1.f;
    float* optr;
    if (b == 0) {
        optr = g_A + (size_t)p * CMODEL + head * DHEAD;
    } else {
        wg = g_w9[(b - 1) * HW + p];
        optr = g_O + ((size_t)(b - 1) * HW + p) * CMODEL + head * DHEAD;
    }
    float4* o4 = (float4*)(optr + half * 20);

    int any = __syncthreads_count(wg != 0.f);
    if (any == 0) return;

    // stage K/V head tile (16B vectors; CMODEL row = 80 ulonglong2)
    {
        const ulonglong2* gk = (const ulonglong2*)g_k;
        const ulonglong2* gv = (const ulonglong2*)g_v;
        ulonglong2* ks2 = (ulonglong2*)ks;
        ulonglong2* vs2 = (ulonglong2*)vs;
        for (int idx = t; idx < LSEQ * 10; idx += 256) {
            int j = idx / 10, d = idx - j * 10;
            int g = (b * LSEQ + j) * 80 + head * 10 + d;
            ks2[idx] = gk[g];
            vs2[idx] = gv[g];
        }
    }
    __syncthreads();

    if (wg == 0.f) return;
    unsigned umask = __activemask();

    u64 q2[10];
    {
        int qb = (b == 0) ? 0 : 1;
        const ulonglong2* qp = (const ulonglong2*)(
            g_q + ((size_t)qb * HW + p) * CMODEL + head * DHEAD + half * 20);
        #pragma unroll
        for (int d = 0; d < 5; ++d) {
            ulonglong2 qq = qp[d];
            q2[2 * d] = qq.x; q2[2 * d + 1] = qq.y;
        }
    }

    u64 acc2[10];
    #pragma unroll
    for (int d = 0; d < 10; ++d) acc2[d] = 0ULL;
    float l = 0.f;

    #pragma unroll 1
    for (int j = 0; j < LSEQ - 1; j += 2) {
        const ulonglong2* kj0 = (const ulonglong2*)(ks + j * 20 + half * 10);
        const ulonglong2* kj1 = (const ulonglong2*)(ks + (j + 1) * 20 + half * 10);
        u64 sA0 = 0ULL, sB0 = 0ULL, sA1 = 0ULL, sB1 = 0ULL;
        #pragma unroll
        for (int d = 0; d < 5; ++d) {
            ulonglong2 k0v = kj0[d], k1v = kj1[d];
            sA0 = ffma2(q2[2 * d], k0v.x, sA0); sB0 = ffma2(q2[2 * d + 1], k0v.y, sB0);
            sA1 = ffma2(q2[2 * d], k1v.x, sA1); sB1 = ffma2(q2[2 * d + 1], k1v.y, sB1);
        }
        float2 fa0 = unpk2(sA0), fb0 = unpk2(sB0);
        float2 fa1 = unpk2(sA1), fb1 = unpk2(sB1);
        float part0 = (fa0.x + fa0.y) + (fb0.x + fb0.y);
        float part1 = (fa1.x + fa1.y) + (fb1.x + fb1.y);
        part0 += __shfl_xor_sync(umask, part0, 1);
        part1 += __shfl_xor_sync(umask, part1, 1);
        float pe0 = __expf(part0 * scale);
        float pe1 = __expf(part1 * scale);
        l += pe0 + pe1;
        u64 pe20 = pack2(pe0, pe0), pe21 = pack2(pe1, pe1);
        const ulonglong2* vj0 = (const ulonglong2*)(vs + j * 20 + half * 10);
        const ulonglong2* vj1 = (const ulonglong2*)(vs + (j + 1) * 20 + half * 10);
        #pragma unroll
        for (int d = 0; d < 5; ++d) {
            ulonglong2 v0 = vj0[d], v1 = vj1[d];
            acc2[2 * d]     = ffma2(pe20, v0.x, acc2[2 * d]);
            acc2[2 * d + 1] = ffma2(pe20, v0.y, acc2[2 * d + 1]);
            acc2[2 * d]     = ffma2(pe21, v1.x, acc2[2 * d]);
            acc2[2 * d + 1] = ffma2(pe21, v1.y, acc2[2 * d + 1]);
        }
    }
    {   // tail key j = 76
        const int j = LSEQ - 1;
        const ulonglong2* kj = (const ulonglong2*)(ks + j * 20 + half * 10);
        u64 sA = 0ULL, sB = 0ULL;
        #pragma unroll
        for (int d = 0; d < 5; ++d) {
            ulonglong2 kk = kj[d];
            sA = ffma2(q2[2 * d], kk.x, sA);
            sB = ffma2(q2[2 * d + 1], kk.y, sB);
        }
        float2 fa = unpk2(sA), fb = unpk2(sB);
        float part = (fa.x + fa.y) + (fb.x + fb.y);
        part += __shfl_xor_sync(umask, part, 1);
        float pe = __expf(part * scale);
        l += pe;
        u64 pe2 = pack2(pe, pe);
        const ulonglong2* vj = (const ulonglong2*)(vs + j * 20 + half * 10);
        #pragma unroll
        for (int d = 0; d < 5; ++d) {
            ulonglong2 vv = vj[d];
            acc2[2 * d]     = ffma2(pe2, vv.x, acc2[2 * d]);
            acc2[2 * d + 1] = ffma2(pe2, vv.y, acc2[2 * d + 1]);
        }
    }

    float inv = 1.f / l;
    float sc = (b == 0) ? inv : wg * inv;   // pre-weighted; reduce kernel just sums
    #pragma unroll
    for (int d = 0; d < 5; ++d) {
        float2 x = unpk2(acc2[2 * d]);
        float2 y = unpk2(acc2[2 * d + 1]);
        o4[d] = make_float4(x.x * sc, x.y * sc, y.x * sc, y.y * sc);
    }
}

// ---------------- sum the 9 pre-weighted batch outputs (w-aware) -----------
__global__ void __launch_bounds__(256) reduce9_kernel()
{
    int idx = blockIdx.x * 256 + threadIdx.x;   // over HW*CMODEL/4 float4s
    int p = idx / (CMODEL / 4);                 // pixel of this float4
    const float4* o4 = (const float4*)g_O;
    const size_t stride = (size_t)HW * CMODEL / 4;
    float4 s = make_float4(0.f, 0.f, 0.f, 0.f);
    #pragma unroll
    for (int bb = 0; bb < NPHASE; ++bb) {
        if (g_w9[bb * HW + p] != 0.f) {         // skip exactly-zero rows (~85%)
            float4 v = o4[bb * stride + idx];
            s.x += v.x; s.y += v.y; s.z += v.z; s.w += v.w;
        }
    }
    ((float4*)(g_A + (size_t)HW * CMODEL))[idx] = s;
}

// ---------------- launch ---------------------------------------------------
extern "C" void kernel_launch(void* const* d_in, const int* in_sizes, int n_in,
                              void* d_out, int out_size)
{
    (void)in_sizes; (void)n_in; (void)out_size;
    const float* hs  = (const float*)d_in[0];
    const float* ehs = (const float*)d_in[1];
    const float* bb  = (const float*)d_in[2];
    const float* Wq  = (const float*)d_in[3];
    const float* Wk  = (const float*)d_in[4];
    const float* Wv  = (const float*)d_in[5];
    const float* Wo  = (const float*)d_in[6];
    const float* bo  = (const float*)d_in[7];
    float* out = (float*)d_out;

    weights_kernel<<<16, 256>>>(bb);

    dim3 gblk(8, 16);    // 128 threads, 8x8 micro
    qproj_kernel<<<dim3(CMODEL / 64, (2 * HW) / 128), gblk>>>(hs, Wq);
    kvproj_kernel<<<dim3(CMODEL / 64, (NB * LSEQ + 31) / 32), dim3(16, 16)>>>(ehs, Wk, Wv);

    att_kernel<<<dim3(HW / 128, HEADS, NB), 256>>>();

    reduce9_kernel<<<(HW * CMODEL / 4) / 256, 256>>>();

    outproj_kernel<<<dim3(CMODEL / 64, (2 * HW) / 128), gblk>>>(Wo, bo, out);
}